// round 1
// baseline (speedup 1.0000x reference)
#include <cuda_runtime.h>
#include <cuda_fp16.h>

#define BB 128
#define NN 1024
#define MM 1024

// Scratch (static __device__ arrays per harness rules; no allocs anywhere)
__device__ __half2 g_K[(size_t)BB * NN * MM / 2];  // 256 MB, K in fp16 for iterations
__device__ float   g_u[BB * NN];
__device__ float   g_v[BB * MM];

// ---------------------------------------------------------------------------
// K = exp(-C/eps) in fp16, written as uint2 (8B) per 4 elements.
// 33554432 float4 groups total.
__global__ void k_prep(const float* __restrict__ C) {
    size_t i = (size_t)blockIdx.x * blockDim.x + threadIdx.x;
    const float4* C4 = (const float4*)C;
    float4 c = C4[i];
    __half2 h0 = __floats2half2_rn(__expf(-20.0f * c.x), __expf(-20.0f * c.y));
    __half2 h1 = __floats2half2_rn(__expf(-20.0f * c.z), __expf(-20.0f * c.w));
    uint2 o;
    o.x = *reinterpret_cast<unsigned int*>(&h0);
    o.y = *reinterpret_cast<unsigned int*>(&h1);
    ((uint2*)g_K)[i] = o;
}

// v0 = 1/M. (u is fully overwritten before first read, no init needed.)
__global__ void k_init_v() {
    int i = blockIdx.x * blockDim.x + threadIdx.x;
    g_v[i] = 1.0f / (float)MM;
}

// ---------------------------------------------------------------------------
// u[b][n] = 1 / (sum_m K[b][n][m] * v[b][m] + 1e-8)
// warp-per-row; v staged in shared as float2 (conflict-free vs half2 index).
// grid = 16384 blocks x 256 threads (8 rows/block, 128 blocks/batch).
__global__ void k_u() {
    __shared__ float2 vs[MM / 2];
    int b = blockIdx.x >> 7;
    const float2* vg = (const float2*)(g_v + (size_t)b * MM);
    for (int i = threadIdx.x; i < MM / 2; i += 256) vs[i] = vg[i];
    __syncthreads();

    int warp = threadIdx.x >> 5;
    int lane = threadIdx.x & 31;
    int row  = (blockIdx.x << 3) + warp;              // global row in [0, B*N)
    const __half2* kr = g_K + (size_t)row * (MM / 2);

    float acc = 0.0f;
#pragma unroll
    for (int j = 0; j < 16; ++j) {
        int idx = lane + 32 * j;                      // coalesced 128B per load
        float2 kf = __half22float2(kr[idx]);
        float2 vv = vs[idx];
        acc = fmaf(kf.x, vv.x, acc);
        acc = fmaf(kf.y, vv.y, acc);
    }
#pragma unroll
    for (int off = 16; off; off >>= 1)
        acc += __shfl_xor_sync(0xffffffffu, acc, off);
    if (lane == 0) g_u[row] = 1.0f / (acc + 1e-8f);
}

// ---------------------------------------------------------------------------
// v[b][m] = 1 / (sum_n K[b][n][m] * u[b][n] + 1e-8)
// Block: 256 threads = 128 column-pairs (half2) x 2 row-groups of 512 rows.
// grid = 512 blocks (4 column-blocks per batch). Fully coalesced K reads.
__global__ void k_v() {
    __shared__ float  us[NN];
    __shared__ float2 part[128];
    int b      = blockIdx.x >> 2;
    int colblk = blockIdx.x & 3;                      // 256 columns per block
    int t      = threadIdx.x;
    int cid    = t & 127;                             // half2 column id
    int rgrp   = t >> 7;                              // 0 or 1

    for (int i = t; i < NN; i += 256) us[i] = g_u[(size_t)b * NN + i];
    __syncthreads();

    int n0 = rgrp * 512;
    const __half2* kp = g_K + (size_t)b * NN * (MM / 2)
                        + (size_t)n0 * (MM / 2) + colblk * 128 + cid;
    float2 acc = make_float2(0.0f, 0.0f);
#pragma unroll 8
    for (int n = 0; n < 512; ++n) {
        float2 kf = __half22float2(*kp);
        float  un = us[n0 + n];
        acc.x = fmaf(kf.x, un, acc.x);
        acc.y = fmaf(kf.y, un, acc.y);
        kp += (MM / 2);
    }
    if (rgrp) part[cid] = acc;
    __syncthreads();
    if (!rgrp) {
        float2 p = part[cid];
        acc.x += p.x;
        acc.y += p.y;
        int m = colblk * 256 + cid * 2;
        g_v[(size_t)b * MM + m]     = 1.0f / (acc.x + 1e-8f);
        g_v[(size_t)b * MM + m + 1] = 1.0f / (acc.y + 1e-8f);
    }
}

// ---------------------------------------------------------------------------
// out[b][n][m] = u[b][n] * exp(-C/eps) * v[b][m]   (exact fp32 K here)
__global__ void k_final(const float* __restrict__ C, float* __restrict__ out) {
    size_t i = (size_t)blockIdx.x * blockDim.x + threadIdx.x;   // float4 index
    const float4* C4 = (const float4*)C;
    float4 c = C4[i];
    size_t row = i >> 8;                      // 256 float4 per row
    int    m4  = (int)(i & 255);
    float  uu  = g_u[row];
    const float4* v4 = (const float4*)(g_v + (row >> 10) * MM);
    float4 vv = v4[m4];
    float4 o;
    o.x = uu * __expf(-20.0f * c.x) * vv.x;
    o.y = uu * __expf(-20.0f * c.y) * vv.y;
    o.z = uu * __expf(-20.0f * c.z) * vv.z;
    o.w = uu * __expf(-20.0f * c.w) * vv.w;
    ((float4*)out)[i] = o;
}

// ---------------------------------------------------------------------------
extern "C" void kernel_launch(void* const* d_in, const int* in_sizes, int n_in,
                              void* d_out, int out_size) {
    const float* C = (const float*)d_in[0];
    float* out = (float*)d_out;

    const int total4 = BB * NN * MM / 4;              // 33554432 float4 groups

    k_prep<<<total4 / 256, 256>>>(C);
    k_init_v<<<(BB * MM) / 256, 256>>>();
    for (int it = 0; it < 10; ++it) {
        k_u<<<(BB * NN) / 8, 256>>>();                // 16384 blocks
        k_v<<<BB * 4, 256>>>();                       // 512 blocks
    }
    k_final<<<total4 / 256, 256>>>(C, out);
}

// round 2
// speedup vs baseline: 1.0182x; 1.0182x over previous
#include <cuda_runtime.h>
#include <cuda_fp16.h>

#define CH 32                 // batches per chunk (64 MB fp16 K -> L2 resident)
#define NCHUNK 4
#define NN 1024
#define MM 1024
#define TILES 16              // CTAs per batch in fused kernel
#define ROWS_PER_CTA (NN / TILES)        // 64
#define ROWS_PER_WARP (ROWS_PER_CTA / 8) // 8

// Scratch: reused for every chunk (same addresses -> L2-resident working set)
__device__ __half2 g_K[(size_t)CH * NN * MM / 2];  // 64 MB
__device__ float   g_u[CH * NN];
__device__ float   g_v[CH * MM];
__device__ float   g_vsum[CH * MM];                // zero-init, self-resetting
__device__ int     g_cnt[CH];                      // zero-init, self-resetting

// ---------------------------------------------------------------------------
// K = exp(-C/eps) in fp16 for this chunk; also (re)initialize v = 1/M.
// grid covers CH*NN*MM/4 float4 groups = 8M -> 32768 blocks x 256.
__global__ void k_prep(const float* __restrict__ C) {
    int i = blockIdx.x * 256 + threadIdx.x;        // float4 index
    float4 c = ((const float4*)C)[i];
    __half2 h0 = __floats2half2_rn(__expf(-20.0f * c.x), __expf(-20.0f * c.y));
    __half2 h1 = __floats2half2_rn(__expf(-20.0f * c.z), __expf(-20.0f * c.w));
    uint2 o;
    o.x = *reinterpret_cast<unsigned int*>(&h0);
    o.y = *reinterpret_cast<unsigned int*>(&h1);
    ((uint2*)g_K)[i] = o;
    if (i < CH * MM / 4) {
        float iv = 1.0f / (float)MM;
        ((float4*)g_v)[i] = make_float4(iv, iv, iv, iv);
    }
}

// ---------------------------------------------------------------------------
// One Sinkhorn iteration, single pass over K:
//   u[n] = 1/(K[n,:].v_old + eps)  and  vsum[m] += sum_n u[n]*K[n,m]
// Last CTA per batch finishes: v = 1/(vsum+eps), vsum = 0, cnt = 0.
__global__ void k_fused() {
    __shared__ float2 vs[MM / 2];
    __shared__ float2 vacc[8][MM / 2];
    __shared__ int last;
    int t = threadIdx.x, w = t >> 5, lane = t & 31;
    int b = blockIdx.x >> 4, tile = blockIdx.x & 15;

    const float2* vg = (const float2*)(g_v + b * MM);
    for (int i = t; i < MM / 2; i += 256) vs[i] = vg[i];
    for (int i = lane; i < MM / 2; i += 32) vacc[w][i] = make_float2(0.0f, 0.0f);
    __syncthreads();

    int row0 = b * NN + tile * ROWS_PER_CTA + w * ROWS_PER_WARP;
    const __half2* kb = g_K + (size_t)row0 * (MM / 2);

    for (int r = 0; r < ROWS_PER_WARP; ++r) {
        const unsigned int* kr = (const unsigned int*)(kb + (size_t)r * (MM / 2));
        unsigned int kraw[16];
#pragma unroll
        for (int j = 0; j < 16; ++j) kraw[j] = kr[lane + 32 * j];

        float acc = 0.0f;
#pragma unroll
        for (int j = 0; j < 16; ++j) {
            float2 kf = __half22float2(*reinterpret_cast<__half2*>(&kraw[j]));
            float2 vv = vs[lane + 32 * j];
            acc = fmaf(kf.x, vv.x, acc);
            acc = fmaf(kf.y, vv.y, acc);
        }
#pragma unroll
        for (int off = 16; off; off >>= 1)
            acc += __shfl_xor_sync(0xffffffffu, acc, off);
        float u = 1.0f / (acc + 1e-8f);
        if (lane == 0) g_u[row0 + r] = u;

#pragma unroll
        for (int j = 0; j < 16; ++j) {
            float2 kf = __half22float2(*reinterpret_cast<__half2*>(&kraw[j]));
            float2 a = vacc[w][lane + 32 * j];
            a.x = fmaf(u, kf.x, a.x);
            a.y = fmaf(u, kf.y, a.y);
            vacc[w][lane + 32 * j] = a;
        }
    }
    __syncthreads();

    // combine 8 warp copies, push to global accumulator
    float* vsum = g_vsum + b * MM;
    for (int i = t; i < MM / 2; i += 256) {
        float2 s = vacc[0][i];
#pragma unroll
        for (int w2 = 1; w2 < 8; ++w2) {
            float2 p = vacc[w2][i];
            s.x += p.x; s.y += p.y;
        }
        atomicAdd(&vsum[2 * i],     s.x);
        atomicAdd(&vsum[2 * i + 1], s.y);
    }

    // last-CTA-per-batch does the reciprocal + reset (threadFenceReduction idiom)
    __threadfence();
    __syncthreads();
    if (t == 0) last = (atomicAdd(&g_cnt[b], 1) == TILES - 1);
    __syncthreads();
    if (last) {
        __threadfence();
        float* vp = g_v + b * MM;
        for (int i = t; i < MM; i += 256) {
            float s = __ldcg(&vsum[i]);
            vp[i] = 1.0f / (s + 1e-8f);
            __stcg(&vsum[i], 0.0f);
        }
        if (t == 0) __stcg(&g_cnt[b], 0);
    }
}

// ---------------------------------------------------------------------------
// out = u * exp(-C/eps) * v  (exact fp32 K here), chunk-local u/v indices.
__global__ void k_final(const float* __restrict__ C, float* __restrict__ out) {
    int i = blockIdx.x * 256 + threadIdx.x;        // float4 index within chunk
    float4 c = ((const float4*)C)[i];
    int row = i >> 8;                              // local b*1024+n
    int m4  = i & 255;
    float uu = g_u[row];
    float4 vv = ((const float4*)(g_v + (row >> 10) * MM))[m4];
    float4 o;
    o.x = uu * __expf(-20.0f * c.x) * vv.x;
    o.y = uu * __expf(-20.0f * c.y) * vv.y;
    o.z = uu * __expf(-20.0f * c.z) * vv.z;
    o.w = uu * __expf(-20.0f * c.w) * vv.w;
    ((float4*)out)[i] = o;
}

// ---------------------------------------------------------------------------
extern "C" void kernel_launch(void* const* d_in, const int* in_sizes, int n_in,
                              void* d_out, int out_size) {
    const float* C = (const float*)d_in[0];
    float* out = (float*)d_out;

    const size_t chunk_elems = (size_t)CH * NN * MM;   // 32M floats
    const int blocks = (int)(chunk_elems / 4 / 256);   // 32768

    for (int c = 0; c < NCHUNK; ++c) {
        const float* Cc = C + (size_t)c * chunk_elems;
        float* Oc = out + (size_t)c * chunk_elems;
        k_prep<<<blocks, 256>>>(Cc);
        for (int it = 0; it < 10; ++it)
            k_fused<<<CH * TILES, 256>>>();
        k_final<<<blocks, 256>>>(Cc, Oc);
    }
}

// round 3
// speedup vs baseline: 1.1536x; 1.1330x over previous
#include <cuda_runtime.h>
#include <cuda_fp16.h>

#define CH 32                 // batches per chunk (64 MB fp16 K -> L2 resident)
#define NCHUNK 4
#define NN 1024
#define MM 1024
#define TILES 16              // CTAs per batch in fused kernel

// Scratch reused across chunks (same addresses -> L2-resident working set)
__device__ __half2 g_K[(size_t)CH * NN * MM / 2];  // 64 MB
__device__ float   g_u[CH * NN];
__device__ float   g_v[CH * MM];
__device__ float   g_vsum[CH * MM];                // zero-init, self-resetting
__device__ int     g_cnt[CH];                      // zero-init, self-resetting

// ---------------------------------------------------------------------------
// K = exp(-C/eps) fp16 for this chunk; also (re)initialize v = 1/M.
// C read with evict-first policy so it doesn't displace K in L2.
__global__ void k_prep(const float* __restrict__ C) {
    int i = blockIdx.x * 256 + threadIdx.x;        // float4 index
    float4 c = __ldcs(((const float4*)C) + i);
    __half2 h0 = __floats2half2_rn(__expf(-20.0f * c.x), __expf(-20.0f * c.y));
    __half2 h1 = __floats2half2_rn(__expf(-20.0f * c.z), __expf(-20.0f * c.w));
    uint2 o;
    o.x = *reinterpret_cast<unsigned int*>(&h0);
    o.y = *reinterpret_cast<unsigned int*>(&h1);
    ((uint2*)g_K)[i] = o;
    if (i < CH * MM / 4) {
        float iv = 1.0f / (float)MM;
        ((float4*)g_v)[i] = make_float4(iv, iv, iv, iv);
    }
}

// ---------------------------------------------------------------------------
// One Sinkhorn iteration, one pass over K:
//   u[n] = 1/(K[n,:].v_old + eps);  vsum[m] += sum_n u[n]*K[n,m]
// v-accumulator lives in registers (lane owns fixed columns lane+32j).
// Last CTA per batch: v = 1/(vsum+eps), reset vsum/cnt.
__global__ void __launch_bounds__(256, 2) k_fused() {
    __shared__ float2 vs[MM / 2];          // 4 KB
    __shared__ float2 vred[8][MM / 2];     // 32 KB, end-of-kernel combine
    __shared__ int last;
    int t = threadIdx.x, w = t >> 5, lane = t & 31;
    int b = blockIdx.x >> 4, tile = blockIdx.x & 15;

    const float2* vg = (const float2*)(g_v + b * MM);
    for (int i = t; i < MM / 2; i += 256) vs[i] = vg[i];
    __syncthreads();

    int row0 = b * NN + tile * 64 + w * 8;
    const unsigned int* kb = (const unsigned int*)(g_K + (size_t)row0 * (MM / 2));

    float2 vr[16];
#pragma unroll
    for (int j = 0; j < 16; ++j) vr[j] = make_float2(0.0f, 0.0f);

#pragma unroll
    for (int rp = 0; rp < 4; ++rp) {                 // row pairs for ILP
        const unsigned int* r0 = kb + (2 * rp) * (MM / 2);
        const unsigned int* r1 = r0 + (MM / 2);
        unsigned int ka[16], kc[16];
#pragma unroll
        for (int j = 0; j < 16; ++j) { ka[j] = r0[lane + 32 * j]; kc[j] = r1[lane + 32 * j]; }

        float a0 = 0.0f, a1 = 0.0f;
#pragma unroll
        for (int j = 0; j < 16; ++j) {
            float2 vv = vs[lane + 32 * j];
            float2 f0 = __half22float2(*reinterpret_cast<__half2*>(&ka[j]));
            float2 f1 = __half22float2(*reinterpret_cast<__half2*>(&kc[j]));
            a0 = fmaf(f0.x, vv.x, a0); a0 = fmaf(f0.y, vv.y, a0);
            a1 = fmaf(f1.x, vv.x, a1); a1 = fmaf(f1.y, vv.y, a1);
        }
#pragma unroll
        for (int off = 16; off; off >>= 1) {
            a0 += __shfl_xor_sync(0xffffffffu, a0, off);
            a1 += __shfl_xor_sync(0xffffffffu, a1, off);
        }
        float u0 = 1.0f / (a0 + 1e-8f);
        float u1 = 1.0f / (a1 + 1e-8f);
        if (lane == 0) { g_u[row0 + 2 * rp] = u0; g_u[row0 + 2 * rp + 1] = u1; }

#pragma unroll
        for (int j = 0; j < 16; ++j) {
            float2 f0 = __half22float2(*reinterpret_cast<__half2*>(&ka[j]));
            float2 f1 = __half22float2(*reinterpret_cast<__half2*>(&kc[j]));
            vr[j].x = fmaf(u0, f0.x, vr[j].x); vr[j].y = fmaf(u0, f0.y, vr[j].y);
            vr[j].x = fmaf(u1, f1.x, vr[j].x); vr[j].y = fmaf(u1, f1.y, vr[j].y);
        }
    }

    // CTA combine of the 8 per-warp register accumulators, then global atomics
#pragma unroll
    for (int j = 0; j < 16; ++j) vred[w][lane + 32 * j] = vr[j];
    __syncthreads();
    float* vsum = g_vsum + b * MM;
    for (int i = t; i < MM / 2; i += 256) {
        float2 s = vred[0][i];
#pragma unroll
        for (int w2 = 1; w2 < 8; ++w2) { s.x += vred[w2][i].x; s.y += vred[w2][i].y; }
        atomicAdd(reinterpret_cast<float2*>(&vsum[2 * i]), s);   // sm_90+ vector RED
    }

    // last-CTA-per-batch does the reciprocal + reset
    __threadfence();
    __syncthreads();
    if (t == 0) last = (atomicAdd(&g_cnt[b], 1) == TILES - 1);
    __syncthreads();
    if (last) {
        __threadfence();
        float* vp = g_v + b * MM;
        for (int i = t; i < MM; i += 256) {
            float s = __ldcg(&vsum[i]);
            vp[i] = 1.0f / (s + 1e-8f);
            __stcg(&vsum[i], 0.0f);
        }
        if (t == 0) __stcg(&g_cnt[b], 0);
    }
}

// ---------------------------------------------------------------------------
// out = u * K * v, reading fp16 K from L2-hot scratch (no C re-read).
// Each thread: one uint4 of K (8 halves) -> two float4 stores.
__global__ void k_final(float* __restrict__ out) {
    int i = blockIdx.x * 256 + threadIdx.x;        // uint4 index within chunk
    uint4 kq = ((const uint4*)g_K)[i];
    int row = i >> 7;                              // 128 uint4 per row
    int c8  = (i & 127) * 8;
    float uu = g_u[row];
    const float4* vp = (const float4*)(g_v + (row >> 10) * MM + c8);
    float4 v0 = vp[0], v1 = vp[1];
    __half2* kh = (__half2*)&kq;
    float2 f0 = __half22float2(kh[0]), f1 = __half22float2(kh[1]);
    float2 f2 = __half22float2(kh[2]), f3 = __half22float2(kh[3]);
    float4 o0 = make_float4(uu * f0.x * v0.x, uu * f0.y * v0.y,
                            uu * f1.x * v0.z, uu * f1.y * v0.w);
    float4 o1 = make_float4(uu * f2.x * v1.x, uu * f2.y * v1.y,
                            uu * f3.x * v1.z, uu * f3.y * v1.w);
    __stcs(((float4*)out) + 2 * i, o0);
    __stcs(((float4*)out) + 2 * i + 1, o1);
}

// ---------------------------------------------------------------------------
extern "C" void kernel_launch(void* const* d_in, const int* in_sizes, int n_in,
                              void* d_out, int out_size) {
    const float* C = (const float*)d_in[0];
    float* out = (float*)d_out;

    const size_t chunk_elems = (size_t)CH * NN * MM;   // 32M floats
    const int prep_blocks  = (int)(chunk_elems / 4 / 256);  // 32768
    const int final_blocks = (int)(chunk_elems / 8 / 256);  // 16384

    for (int c = 0; c < NCHUNK; ++c) {
        const float* Cc = C + (size_t)c * chunk_elems;
        float* Oc = out + (size_t)c * chunk_elems;
        k_prep<<<prep_blocks, 256>>>(Cc);
        for (int it = 0; it < 10; ++it)
            k_fused<<<CH * TILES, 256>>>();
        k_final<<<final_blocks, 256>>>(Oc);
    }
}

// round 5
// speedup vs baseline: 1.1595x; 1.0051x over previous
#include <cuda_runtime.h>
#include <cuda_fp16.h>

#define NN 1024
#define MM 1024

// fp16 K scratch for all 128 batches (256 MB)
__device__ __half2 g_K[(size_t)128 * NN * MM / 2];

// One CTA (1024 threads) per batch. Phases: prep -> 10 fused iterations -> output.
// v lives in shared in a PERMUTED layout: half2-column c = (g*32+L)*4+h is stored
// at vperm[g*128 + h*32 + L]  (g=0..3 uint4-group, h=0..3 half2-in-uint4, L=lane).
// The same layout is used everywhere (combine tree, output), so nothing is ever
// un-permuted and every shared access is conflict-free.
__global__ void __launch_bounds__(1024, 1) k_sink(const float* __restrict__ C,
                                                  float* __restrict__ out) {
    __shared__ float2 vperm[512];        // 4 KB   current v (permuted)
    __shared__ float  u_s[NN];           // 4 KB   current u
    __shared__ float2 sbuf[8][512];      // 32 KB  warp-combine buffers (permuted)

    int b = blockIdx.x;
    int t = threadIdx.x, w = t >> 5, L = t & 31;

    // ---------------- prep: K = exp(-C/eps) in fp16 ----------------
    const float4* C4 = (const float4*)(C + (size_t)b * NN * MM);
    uint2* K2 = (uint2*)(g_K + (size_t)b * (NN * MM / 2));
    for (int k = 0; k < 256; ++k) {
        int i = t + 1024 * k;
        float4 c = __ldcs(C4 + i);
        __half2 h0 = __floats2half2_rn(__expf(-20.0f * c.x), __expf(-20.0f * c.y));
        __half2 h1 = __floats2half2_rn(__expf(-20.0f * c.z), __expf(-20.0f * c.w));
        uint2 o;
        o.x = *reinterpret_cast<unsigned int*>(&h0);
        o.y = *reinterpret_cast<unsigned int*>(&h1);
        K2[i] = o;
    }
    if (t < 512) vperm[t] = make_float2(1.0f / 1024.0f, 1.0f / 1024.0f);
    __syncthreads();

    const uint4* Kb = (const uint4*)K2;   // 128 uint4 per row

    // ---------------- 10 fused Sinkhorn iterations ----------------
    for (int it = 0; it < 10; ++it) {
        float2 vr[16];                    // per-lane v-partial (32 cols, permuted)
#pragma unroll
        for (int j = 0; j < 16; ++j) vr[j] = make_float2(0.0f, 0.0f);

        // each warp owns 32 rows
        for (int rr = 0; rr < 32; ++rr) {
            int row = (w << 5) + rr;
            const uint4* Kr = Kb + row * 128;

            // pass 1: row dot v  (two accumulators to shorten the FFMA chain)
            float a0 = 0.0f, a1 = 0.0f;
#pragma unroll
            for (int g = 0; g < 4; ++g) {
                uint4 kq = Kr[(g << 5) + L];
                const __half2* kh = (const __half2*)&kq;
                float& acc = (g < 2) ? a0 : a1;
#pragma unroll
                for (int h = 0; h < 4; ++h) {
                    float2 kf = __half22float2(kh[h]);
                    float2 vv = vperm[(g << 7) + (h << 5) + L];
                    acc = fmaf(kf.x, vv.x, acc);
                    acc = fmaf(kf.y, vv.y, acc);
                }
            }
            float a = a0 + a1;
#pragma unroll
            for (int off = 16; off; off >>= 1)
                a += __shfl_xor_sync(0xffffffffu, a, off);
            float u = 1.0f / (a + 1e-8f);
            if (L == 0) u_s[row] = u;

            // pass 2: re-read row (L1-hot) and accumulate u*K into vr
#pragma unroll
            for (int g = 0; g < 4; ++g) {
                uint4 kq = Kr[(g << 5) + L];
                const __half2* kh = (const __half2*)&kq;
#pragma unroll
                for (int h = 0; h < 4; ++h) {
                    float2 kf = __half22float2(kh[h]);
                    vr[(g << 2) + h].x = fmaf(u, kf.x, vr[(g << 2) + h].x);
                    vr[(g << 2) + h].y = fmaf(u, kf.y, vr[(g << 2) + h].y);
                }
            }
        }

        // combine the 32 warps' register partials -> new v (all intra-CTA)
        __syncthreads();                  // prior vperm/sbuf readers done
        if (w < 8) {
#pragma unroll
            for (int g = 0; g < 4; ++g)
#pragma unroll
                for (int h = 0; h < 4; ++h)
                    sbuf[w][(g << 7) + (h << 5) + L] = vr[(g << 2) + h];
        }
        __syncthreads();
#pragma unroll
        for (int s = 1; s < 4; ++s) {     // three serialized add-stages
            if ((w >> 3) == s) {
                int d = w & 7;
#pragma unroll
                for (int g = 0; g < 4; ++g)
#pragma unroll
                    for (int h = 0; h < 4; ++h) {
                        int idx = (g << 7) + (h << 5) + L;
                        float2 p = sbuf[d][idx];
                        p.x += vr[(g << 2) + h].x;
                        p.y += vr[(g << 2) + h].y;
                        sbuf[d][idx] = p;
                    }
            }
            __syncthreads();
        }
        if (t < 512) {
            float2 s = sbuf[0][t];
#pragma unroll
            for (int k = 1; k < 8; ++k) {
                s.x += sbuf[k][t].x;
                s.y += sbuf[k][t].y;
            }
            vperm[t] = make_float2(1.0f / (s.x + 1e-8f), 1.0f / (s.y + 1e-8f));
        }
        __syncthreads();
    }

    // ---------------- output: out = u * K * v ----------------
    float4* O4 = (float4*)(out + (size_t)b * NN * MM);
    for (int k = 0; k < 128; ++k) {
        int i = t + 1024 * k;             // uint4 index within the batch
        uint4 kq = Kb[i];
        int row = i >> 7;
        int j   = i & 127;                // uint4 within row = g*32 + L
        int g   = j >> 5, Lj = j & 31;
        float u = u_s[row];
        const __half2* kh = (const __half2*)&kq;
        float4 o0, o1;
        float2 f, vv;
        f = __half22float2(kh[0]); vv = vperm[(g << 7) + 0  + Lj];
        o0.x = u * f.x * vv.x;  o0.y = u * f.y * vv.y;
        f = __half22float2(kh[1]); vv = vperm[(g << 7) + 32 + Lj];
        o0.z = u * f.x * vv.x;  o0.w = u * f.y * vv.y;
        f = __half22float2(kh[2]); vv = vperm[(g << 7) + 64 + Lj];
        o1.x = u * f.x * vv.x;  o1.y = u * f.y * vv.y;
        f = __half22float2(kh[3]); vv = vperm[(g << 7) + 96 + Lj];
        o1.z = u * f.x * vv.x;  o1.w = u * f.y * vv.y;
        __stcs(O4 + 2 * i,     o0);
        __stcs(O4 + 2 * i + 1, o1);
    }
}

extern "C" void kernel_launch(void* const* d_in, const int* in_sizes, int n_in,
                              void* d_out, int out_size) {
    const float* C = (const float*)d_in[0];
    float* out = (float*)d_out;
    k_sink<<<128, 1024>>>(C, out);
}